// round 1
// baseline (speedup 1.0000x reference)
#include <cuda_runtime.h>

// Cost-volume construction:
//   out[0, c,      d, h, w] = imgl[0, c, h, w]                      (broadcast over d)
//   out[0, c + 32, d, h, w] = (w >= d) ? imgr[0, c, h, w - d] : 0
// Shapes: imgl/imgr (1, 32, 256, 480) f32, out (1, 64, 32, 256, 480) f32.
//
// Pure store-bandwidth-bound: ~1.007 GB written, 31.5 MB read (L2-resident).
// One thread per (c, h, w4): 2 aligned float4 loads + 31 scalar L2-hit loads,
// 64 coalesced STG.128 stores. Right-half shift handled by a sliding 4-float
// register window (window moves by exactly one element per disparity step).

constexpr int C  = 32;
constexpr int D  = 32;
constexpr int H2 = 256;
constexpr int W2 = 480;
constexpr int W4 = W2 / 4;                 // 120 float4 per row
constexpr long long PLANE = (long long)H2 * W2;      // 122880
constexpr long long CH    = (long long)D * PLANE;    // 3,932,160 floats per out-channel

__global__ __launch_bounds__(256) void cost_volume_kernel(
    const float* __restrict__ imgl,
    const float* __restrict__ imgr,
    float* __restrict__ out)
{
    int idx = blockIdx.x * blockDim.x + threadIdx.x;
    if (idx >= C * H2 * W4) return;

    int w4 = idx % W4;
    int t  = idx / W4;
    int h  = t % H2;
    int c  = t / H2;
    int w  = w4 * 4;

    // ---- Left half: broadcast one float4 across all D disparity slices ----
    const float4 l = *reinterpret_cast<const float4*>(
        imgl + (long long)c * PLANE + (long long)h * W2 + w);

    float* outL = out + (long long)c * CH + (long long)h * W2 + w;
#pragma unroll
    for (int d = 0; d < D; ++d) {
        *reinterpret_cast<float4*>(outL + (long long)d * PLANE) = l;
    }

    // ---- Right half: sliding register window over shifted imgr row ----
    const float* rrow = imgr + (long long)c * PLANE + (long long)h * W2;
    float* outR = out + (long long)(c + C) * CH + (long long)h * W2 + w;

    float4 r = *reinterpret_cast<const float4*>(rrow + w);   // d = 0 (aligned)
    *reinterpret_cast<float4*>(outR) = r;

#pragma unroll
    for (int d = 1; d < D; ++d) {
        // window slides left by one: positions [w-d, w-d+3]
        r.w = r.z;
        r.z = r.y;
        r.y = r.x;
        int src = w - d;
        r.x = (src >= 0) ? __ldg(rrow + src) : 0.0f;
        *reinterpret_cast<float4*>(outR + (long long)d * PLANE) = r;
    }
}

extern "C" void kernel_launch(void* const* d_in, const int* in_sizes, int n_in,
                              void* d_out, int out_size)
{
    const float* imgl = (const float*)d_in[0];
    const float* imgr = (const float*)d_in[1];
    float* out = (float*)d_out;

    const int total  = C * H2 * W4;          // 983,040 threads
    const int block  = 256;
    const int grid   = (total + block - 1) / block;  // 3840 blocks
    cost_volume_kernel<<<grid, block>>>(imgl, imgr, out);
}

// round 2
// speedup vs baseline: 1.0276x; 1.0276x over previous
#include <cuda_runtime.h>

// Cost-volume construction:
//   out[0, c,      d, h, w] = imgl[0, c, h, w]                      (broadcast over d)
//   out[0, c + 32, d, h, w] = (w >= d) ? imgr[0, c, h, w - d] : 0
// Shapes: imgl/imgr (1, 32, 256, 480) f32, out (1, 64, 32, 256, 480) f32.
//
// R2 changes vs R1 (168us, DRAM 78%, occ 57%, regs 48):
//  - 32-bit indexing everywhere (output = 1.007 GB < 2^31 bytes)
//  - each thread handles 16 disparities (split in 2), so all strided store
//    offsets fit the +/-8MB STG immediate window (15 * 491520B = 7.37MB):
//    one base register per half, immediates for the rest -> far fewer regs
//  - 2x threads -> more warps with stores in flight -> higher DRAM occupancy

constexpr int C  = 32;
constexpr int D  = 32;
constexpr int H2 = 256;
constexpr int W2 = 480;
constexpr int W4 = W2 / 4;              // 120 float4 per row
constexpr int PLANE = H2 * W2;          // 122880 floats
constexpr int CH    = D * PLANE;        // 3,932,160 floats per out-channel
constexpr int DSPLIT = 16;              // disparities per thread

__global__ __launch_bounds__(256) void cost_volume_kernel(
    const float* __restrict__ imgl,
    const float* __restrict__ imgr,
    float* __restrict__ out)
{
    int idx = blockIdx.x * blockDim.x + threadIdx.x;

    int w4 = idx % W4;
    int t  = idx / W4;
    int h  = t % H2;
    t /= H2;
    int c     = t % C;
    int split = t / C;                  // 0 or 1
    int w  = w4 * 4;
    int d0 = split * DSPLIT;

    // ---- Left half: broadcast one float4 across DSPLIT disparity slices ----
    const float4 l = *reinterpret_cast<const float4*>(imgl + c * PLANE + h * W2 + w);

    float* outL = out + c * CH + d0 * PLANE + h * W2 + w;
#pragma unroll
    for (int i = 0; i < DSPLIT; ++i) {
        *reinterpret_cast<float4*>(outL + i * PLANE) = l;   // const offsets -> STG [reg+imm]
    }

    // ---- Right half: sliding register window over shifted imgr row ----
    const float* rrow = imgr + c * PLANE + h * W2;
    float* outR = out + (c + C) * CH + d0 * PLANE + h * W2 + w;

    // initial window: positions [w-d0, w-d0+3], zero-filled where negative
    int s = w - d0;
    float4 r;
    r.x = (s     >= 0) ? rrow[s]     : 0.0f;
    r.y = (s + 1 >= 0) ? rrow[s + 1] : 0.0f;
    r.z = (s + 2 >= 0) ? rrow[s + 2] : 0.0f;
    r.w = (s + 3 >= 0) ? rrow[s + 3] : 0.0f;
    *reinterpret_cast<float4*>(outR) = r;

#pragma unroll
    for (int i = 1; i < DSPLIT; ++i) {
        // window slides left by one element per disparity step
        r.w = r.z;
        r.z = r.y;
        r.y = r.x;
        int src = s - i;
        r.x = (src >= 0) ? __ldg(rrow + src) : 0.0f;
        *reinterpret_cast<float4*>(outR + i * PLANE) = r;
    }
}

extern "C" void kernel_launch(void* const* d_in, const int* in_sizes, int n_in,
                              void* d_out, int out_size)
{
    const float* imgl = (const float*)d_in[0];
    const float* imgr = (const float*)d_in[1];
    float* out = (float*)d_out;

    const int total = 2 * C * H2 * W4;          // 1,966,080 threads
    const int block = 256;
    const int grid  = (total + block - 1) / block;  // 7680 blocks
    cost_volume_kernel<<<grid, block>>>(imgl, imgr, out);
}

// round 3
// speedup vs baseline: 1.0439x; 1.0159x over previous
#include <cuda_runtime.h>

// Cost-volume construction:
//   out[0, c,      d, h, w] = imgl[0, c, h, w]                      (broadcast over d)
//   out[0, c + 32, d, h, w] = (w >= d) ? imgr[0, c, h, w - d] : 0
// Shapes: imgl/imgr (1, 32, 256, 480) f32, out (1, 64, 32, 256, 480) f32.
//
// R3 changes vs R2 (163.5us, DRAM 79.5%, occ 42%, regs 62):
//  - DSPLIT 16 -> 8 (fewer live store addresses) + __launch_bounds__(256, 8)
//    to force regs <= 32 -> 64 warps/SM theoretical occupancy
//  - __stcs streaming (evict-first) stores: output is write-once, never
//    re-read; don't let L2 retain it, improve drain to DRAM

constexpr int C  = 32;
constexpr int D  = 32;
constexpr int H2 = 256;
constexpr int W2 = 480;
constexpr int W4 = W2 / 4;              // 120 float4 per row
constexpr int PLANE = H2 * W2;          // 122880 floats
constexpr int CH    = D * PLANE;        // 3,932,160 floats per out-channel
constexpr int DSPLIT = 8;               // disparities per thread
constexpr int NSPLIT = D / DSPLIT;      // 4

__global__ __launch_bounds__(256, 8) void cost_volume_kernel(
    const float* __restrict__ imgl,
    const float* __restrict__ imgr,
    float* __restrict__ out)
{
    int idx = blockIdx.x * blockDim.x + threadIdx.x;

    int w4 = idx % W4;
    int t  = idx / W4;
    int h  = t % H2;
    t /= H2;
    int c     = t % C;
    int split = t / C;                  // 0..3
    int w  = w4 * 4;
    int d0 = split * DSPLIT;

    // ---- Left half: broadcast one float4 across DSPLIT disparity slices ----
    const float4 l = *reinterpret_cast<const float4*>(imgl + c * PLANE + h * W2 + w);

    float* outL = out + c * CH + d0 * PLANE + h * W2 + w;
#pragma unroll
    for (int i = 0; i < DSPLIT; ++i) {
        __stcs(reinterpret_cast<float4*>(outL + i * PLANE), l);
    }

    // ---- Right half: sliding register window over shifted imgr row ----
    const float* rrow = imgr + c * PLANE + h * W2;
    float* outR = out + (c + C) * CH + d0 * PLANE + h * W2 + w;

    // initial window: positions [w-d0, w-d0+3], zero-filled where negative
    int s = w - d0;
    float4 r;
    r.x = (s     >= 0) ? rrow[s]     : 0.0f;
    r.y = (s + 1 >= 0) ? rrow[s + 1] : 0.0f;
    r.z = (s + 2 >= 0) ? rrow[s + 2] : 0.0f;
    r.w = (s + 3 >= 0) ? rrow[s + 3] : 0.0f;
    __stcs(reinterpret_cast<float4*>(outR), r);

#pragma unroll
    for (int i = 1; i < DSPLIT; ++i) {
        // window slides left by one element per disparity step
        r.w = r.z;
        r.z = r.y;
        r.y = r.x;
        int src = s - i;
        r.x = (src >= 0) ? __ldg(rrow + src) : 0.0f;
        __stcs(reinterpret_cast<float4*>(outR + i * PLANE), r);
    }
}

extern "C" void kernel_launch(void* const* d_in, const int* in_sizes, int n_in,
                              void* d_out, int out_size)
{
    const float* imgl = (const float*)d_in[0];
    const float* imgr = (const float*)d_in[1];
    float* out = (float*)d_out;

    const int total = NSPLIT * C * H2 * W4;          // 3,932,160 threads
    const int block = 256;
    const int grid  = (total + block - 1) / block;   // 15360 blocks
    cost_volume_kernel<<<grid, block>>>(imgl, imgr, out);
}